// round 6
// baseline (speedup 1.0000x reference)
#include <cuda_runtime.h>
#include <cstdint>
#include <math.h>

#define B_   256
#define T_   512
#define D_   128
#define H_   1024
#define G_   3072
#define O_   128
#define DIN  257
#define KIN  320

#define BKS     32
#define SPITCH  40
#define A_FL    (64 * SPITCH)
#define B_FL    (96 * SPITCH)
#define STG_FL  (A_FL + B_FL)
#define SMEM_BYTES (4 * STG_FL * 4)    // 102400

__host__ __device__ __forceinline__ int PERM(int c) {
    return (c & ~7) | (((c & 3) << 1) | ((c >> 2) & 1));
}

// ---------------- scratch ----------------
__device__ float g_gi[(size_t)T_ * B_ * G_];
__device__ float g_xcat[(size_t)(T_ * B_) * KIN];
__device__ float g_wih[(size_t)G_ * KIN];
__device__ float g_w3[(size_t)G_ * H_];
__device__ float g_hf[2][B_ * H_];
__device__ float g_htf[2][B_ * H_];

// ---------------- helpers ----------------
__device__ __forceinline__ uint32_t f2tf(float x) {
    uint32_t u; asm("cvt.rna.tf32.f32 %0, %1;" : "=r"(u) : "f"(x)); return u;
}
__device__ __forceinline__ uint32_t fbits(float x) { return __float_as_uint(x); }
__device__ __forceinline__ float uf(uint32_t x) { return __uint_as_float(x); }
__device__ __forceinline__ float sigmoidf_(float x) { return 1.0f / (1.0f + expf(-x)); }
__device__ __forceinline__ uint32_t smem_u32(const void* p) {
    uint32_t a; asm("{ .reg .u64 t; cvta.to.shared.u64 t, %1; cvt.u32.u64 %0, t; }" : "=r"(a) : "l"(p)); return a;
}
__device__ __forceinline__ void cpa16(uint32_t d, const void* s) {
    asm volatile("cp.async.cg.shared.global [%0], [%1], 16;" :: "r"(d), "l"(s));
}
__device__ __forceinline__ void cpcommit() { asm volatile("cp.async.commit_group;"); }
__device__ __forceinline__ void cpwait2()  { asm volatile("cp.async.wait_group 2;" ::: "memory"); }
__device__ __forceinline__ void cpwait0()  { asm volatile("cp.async.wait_group 0;" ::: "memory"); }

__device__ __forceinline__ void mma_legacy(float& d0, float& d1, float& d2, float& d3,
    uint32_t a0, uint32_t a1, uint32_t a2, uint32_t a3, uint32_t b0, uint32_t b1) {
    asm volatile("mma.sync.aligned.m16n8k8.row.col.f32.tf32.tf32.f32 {%0,%1,%2,%3},{%4,%5,%6,%7},{%8,%9},{%0,%1,%2,%3};\n"
        : "+f"(d0), "+f"(d1), "+f"(d2), "+f"(d3)
        : "r"(a0), "r"(a1), "r"(a2), "r"(a3), "r"(b0), "r"(b1));
}

// ---------------- 256-thread mainloop (gi GEMM): 64M x 96N, warp tile 32x24 ----------------
template<int NSTG>
__device__ __forceinline__ void mainloop256(
    float* sm, uint32_t sbase,
    const float* __restrict__ Ag, int lda,
    const float* __restrict__ B0, const float* __restrict__ B1,
    const float* __restrict__ B2, int ldb,
    int tid, int wm, int wn, float acc[2][3][4])
{
    const int lane = tid & 31;
    const int g4 = lane >> 2, tig = lane & 3;

    auto issue = [&](int s) {
        int buf = s & 3;
        uint32_t ab = sbase + (uint32_t)(buf * STG_FL) * 4u;
        uint32_t bb = ab + A_FL * 4u;
        int kc = s * BKS;
#pragma unroll
        for (int i = 0; i < 2; i++) {
            int f = tid + 256 * i, r = f >> 3, c4 = f & 7;
            cpa16(ab + (uint32_t)(r * SPITCH + c4 * 4) * 4u, Ag + (size_t)r * lda + kc + c4 * 4);
        }
#pragma unroll
        for (int i = 0; i < 3; i++) {
            int f = tid + 256 * i, r = f >> 3, c4 = f & 7;
            const float* base = (r < 32) ? B0 : ((r < 64) ? B1 : B2);
            cpa16(bb + (uint32_t)(r * SPITCH + c4 * 4) * 4u, base + (size_t)(r & 31) * ldb + kc + c4 * 4);
        }
        cpcommit();
    };

    issue(0); issue(1); issue(2);
#pragma unroll 1
    for (int s = 0; s < NSTG; s++) {
        cpwait2();
        __syncthreads();
        const float* sA = sm + (s & 3) * STG_FL;
        const float* sB = sA + A_FL;
#pragma unroll
        for (int k8 = 0; k8 < 4; k8++) {
            const int kb = k8 * 8;
            uint32_t a[2][4];
#pragma unroll
            for (int mt = 0; mt < 2; mt++) {
                float2 v0 = *(const float2*)(sA + (wm + mt * 16 + g4) * SPITCH + kb + 2 * tig);
                float2 v1 = *(const float2*)(sA + (wm + mt * 16 + g4 + 8) * SPITCH + kb + 2 * tig);
                a[mt][0] = fbits(v0.x); a[mt][2] = fbits(v0.y);
                a[mt][1] = fbits(v1.x); a[mt][3] = fbits(v1.y);
            }
#pragma unroll
            for (int nf = 0; nf < 3; nf++) {
                float2 bv = *(const float2*)(sB + (wn + nf * 8 + g4) * SPITCH + kb + 2 * tig);
                uint32_t b0 = fbits(bv.x), b1 = fbits(bv.y);
#pragma unroll
                for (int mt = 0; mt < 2; mt++)
                    mma_legacy(acc[mt][nf][0], acc[mt][nf][1], acc[mt][nf][2], acc[mt][nf][3],
                               a[mt][0], a[mt][1], a[mt][2], a[mt][3], b0, b1);
            }
        }
        if (s + 3 < NSTG) issue(s + 3); else cpcommit();
    }
    cpwait0();
    __syncthreads();
}

// ---------------- pack kernels ----------------
__global__ void pack_x(const float* __restrict__ x, const float* __restrict__ mask, const float* __restrict__ ti) {
    size_t idx = (size_t)blockIdx.x * blockDim.x + threadIdx.x;
    if (idx >= (size_t)(T_ * B_) * KIN) return;
    int k = (int)(idx % KIN);
    size_t row = idx / KIN;
    int t = (int)(row >> 8), b = (int)(row & 255);
    float v = 0.f;
    if (k < 128) v = x[((size_t)b * T_ + t) * D_ + k];
    else if (k < 256) v = mask[((size_t)b * T_ + t) * D_ + (k - 128)];
    else if (k == 256) v = ti[(size_t)b * T_ + t];
    g_xcat[row * KIN + PERM(k)] = uf(f2tf(v));
}
__global__ void pack_w(const float* __restrict__ W_ih) {
    size_t idx = (size_t)blockIdx.x * blockDim.x + threadIdx.x;
    if (idx >= (size_t)G_ * KIN) return;
    int k = (int)(idx % KIN); size_t g = idx / KIN;
    g_wih[g * KIN + PERM(k)] = (k < DIN) ? uf(f2tf(W_ih[g * DIN + k])) : 0.0f;
}
__global__ void pack_w3(const float* __restrict__ W_hh) {
    size_t idx = (size_t)blockIdx.x * blockDim.x + threadIdx.x;
    if (idx >= (size_t)G_ * H_) return;
    int k = (int)(idx % H_); size_t g = idx / H_;
    g_w3[g * H_ + PERM(k)] = uf(f2tf(W_hh[idx]));
}
__global__ void zero_h0() {
    int idx = blockIdx.x * blockDim.x + threadIdx.x;
    if (idx < B_ * H_) { g_hf[0][idx] = 0.0f; g_htf[0][idx] = 0.0f; }
}

// ---------------- gi GEMM (unchanged structure) ----------------
__global__ __launch_bounds__(256) void gi_gemm2(const float* __restrict__ b_ih) {
    extern __shared__ float sm[];
    uint32_t sbase = smem_u32(sm);
    const int tid = threadIdx.x, lane = tid & 31, wid = tid >> 5;
    const int wm = (wid >> 2) * 32, wn = (wid & 3) * 24;
    const int g4 = lane >> 2, tig = lane & 3;
    const size_t m0 = (size_t)blockIdx.x * 64;
    const int n0 = blockIdx.y * 96;

    float acc[2][3][4];
#pragma unroll
    for (int i = 0; i < 2; i++)
#pragma unroll
        for (int j = 0; j < 3; j++)
#pragma unroll
            for (int e = 0; e < 4; e++) acc[i][j][e] = 0.f;

    mainloop256<KIN / BKS>(sm, sbase, g_xcat + m0 * KIN, KIN,
                           g_wih + (size_t)n0 * KIN,
                           g_wih + (size_t)(n0 + 32) * KIN,
                           g_wih + (size_t)(n0 + 64) * KIN, KIN,
                           tid, wm, wn, acc);

#pragma unroll
    for (int mt = 0; mt < 2; mt++)
#pragma unroll
        for (int nf = 0; nf < 3; nf++)
#pragma unroll
            for (int e = 0; e < 4; e++) {
                size_t row = m0 + wm + mt * 16 + g4 + ((e >> 1) << 3);
                int col = n0 + wn + nf * 8 + 2 * tig + (e & 1);
                g_gi[row * G_ + col] = acc[mt][nf][e] + b_ih[col];
            }
}

// ---------------- fused GRU step: 512 threads, 16 warps (4m x 4n), warp tile 16x24 ----------------
__global__ __launch_bounds__(512) void gru_step3(int t, const float* __restrict__ bhh) {
    extern __shared__ float sm[];
    uint32_t sbase = smem_u32(sm);
    const int tid = threadIdx.x, lane = tid & 31, wid = tid >> 5;
    const int wm = (wid >> 2) * 16, wn = (wid & 3) * 24;
    const int g4 = lane >> 2, tig = lane & 3;
    const int m0 = blockIdx.x * 64, n0 = blockIdx.y * 32;

    const float* __restrict__ Ag = g_htf[t & 1] + (size_t)m0 * H_;
    const float* __restrict__ B0 = g_w3 + (size_t)n0 * H_;
    const float* __restrict__ B1 = g_w3 + (size_t)(H_ + n0) * H_;
    const float* __restrict__ B2 = g_w3 + (size_t)(2 * H_ + n0) * H_;

    float acc[3][4];
#pragma unroll
    for (int j = 0; j < 3; j++)
#pragma unroll
        for (int e = 0; e < 4; e++) acc[j][e] = 0.f;

    auto issue = [&](int s) {
        int buf = s & 3;
        uint32_t ab = sbase + (uint32_t)(buf * STG_FL) * 4u;
        uint32_t bb = ab + A_FL * 4u;
        int kc = s * BKS;
        {   // A: 512 float4 = 1 per thread
            int r = tid >> 3, c4 = tid & 7;
            cpa16(ab + (uint32_t)(r * SPITCH + c4 * 4) * 4u, Ag + (size_t)r * H_ + kc + c4 * 4);
        }
        {   // B: 768 float4 = 1.5 per thread
            int f = tid, r = f >> 3, c4 = f & 7;
            const float* base = (r < 32) ? B0 : ((r < 64) ? B1 : B2);
            cpa16(bb + (uint32_t)(r * SPITCH + c4 * 4) * 4u, base + (size_t)(r & 31) * H_ + kc + c4 * 4);
            if (tid < 256) {
                int f2 = tid + 512, r2 = f2 >> 3, c42 = f2 & 7;
                cpa16(bb + (uint32_t)(r2 * SPITCH + c42 * 4) * 4u, B2 + (size_t)(r2 & 31) * H_ + kc + c42 * 4);
            }
        }
        cpcommit();
    };

    issue(0); issue(1); issue(2);
#pragma unroll 1
    for (int s = 0; s < H_ / BKS; s++) {
        cpwait2();
        __syncthreads();
        const float* sA = sm + (s & 3) * STG_FL;
        const float* sB = sA + A_FL;
#pragma unroll
        for (int k8 = 0; k8 < 4; k8++) {
            const int kb = k8 * 8;
            float2 v0 = *(const float2*)(sA + (wm + g4) * SPITCH + kb + 2 * tig);
            float2 v1 = *(const float2*)(sA + (wm + g4 + 8) * SPITCH + kb + 2 * tig);
            uint32_t a0 = fbits(v0.x), a2 = fbits(v0.y);
            uint32_t a1 = fbits(v1.x), a3 = fbits(v1.y);
#pragma unroll
            for (int nf = 0; nf < 3; nf++) {
                float2 bv = *(const float2*)(sB + (wn + nf * 8 + g4) * SPITCH + kb + 2 * tig);
                mma_legacy(acc[nf][0], acc[nf][1], acc[nf][2], acc[nf][3],
                           a0, a1, a2, a3, fbits(bv.x), fbits(bv.y));
            }
        }
        if (s + 3 < H_ / BKS) issue(s + 3); else cpcommit();
    }
    cpwait0();
    __syncthreads();

    // acc -> smem gh tile [64][96] pitch 100
    float* gh = sm;
#pragma unroll
    for (int nf = 0; nf < 3; nf++)
#pragma unroll
        for (int e = 0; e < 4; e++) {
            int row = wm + g4 + ((e >> 1) << 3);
            int col = wn + nf * 8 + 2 * tig + (e & 1);
            gh[row * 100 + col] = acc[nf][e];
        }
    __syncthreads();

    // gate math: first 256 threads, each -> (row r, cols cg..cg+7)
    if (tid < 256) {
        const int r = tid >> 2;
        const int cg = (tid & 3) * 8;
        const int m = m0 + r;
        const float* __restrict__ gi = g_gi + ((size_t)t * B_ + m) * G_ + n0;
        const float* __restrict__ hp = g_hf[t & 1] + (size_t)m * H_ + n0;
        float* __restrict__ ho  = g_hf[(t + 1) & 1] + (size_t)m * H_ + n0;
        float* __restrict__ htf = g_htf[(t + 1) & 1] + (size_t)m * H_ + n0;

        float4 ir0 = *(const float4*)(gi + cg),          ir1 = *(const float4*)(gi + cg + 4);
        float4 iz0 = *(const float4*)(gi + H_ + cg),     iz1 = *(const float4*)(gi + H_ + cg + 4);
        float4 in0 = *(const float4*)(gi + 2 * H_ + cg), in1 = *(const float4*)(gi + 2 * H_ + cg + 4);
        float4 hv0 = *(const float4*)(hp + cg),          hv1 = *(const float4*)(hp + cg + 4);
        float irr[8] = {ir0.x, ir0.y, ir0.z, ir0.w, ir1.x, ir1.y, ir1.z, ir1.w};
        float izz[8] = {iz0.x, iz0.y, iz0.z, iz0.w, iz1.x, iz1.y, iz1.z, iz1.w};
        float inn[8] = {in0.x, in0.y, in0.z, in0.w, in1.x, in1.y, in1.z, in1.w};
        float hvv[8] = {hv0.x, hv0.y, hv0.z, hv0.w, hv1.x, hv1.y, hv1.z, hv1.w};
        float o[8];
#pragma unroll
        for (int j = 0; j < 8; j++) {
            int cc = cg + j;
            float rr = sigmoidf_(irr[j] + gh[r * 100 + cc] + bhh[n0 + cc]);
            float zz = sigmoidf_(izz[j] + gh[r * 100 + 32 + cc] + bhh[H_ + n0 + cc]);
            float nn = tanhf(inn[j] + rr * (gh[r * 100 + 64 + cc] + bhh[2 * H_ + n0 + cc]));
            o[j] = (1.0f - zz) * nn + zz * hvv[j];
        }
        float4 w0 = { o[0], o[1], o[2], o[3] };
        float4 w1 = { o[4], o[5], o[6], o[7] };
        *(float4*)(ho + cg) = w0;
        *(float4*)(ho + cg + 4) = w1;
        float4 p0 = { uf(f2tf(o[0])), uf(f2tf(o[4])), uf(f2tf(o[1])), uf(f2tf(o[5])) };
        float4 p1 = { uf(f2tf(o[2])), uf(f2tf(o[6])), uf(f2tf(o[3])), uf(f2tf(o[7])) };
        *(float4*)(htf + cg) = p0;
        *(float4*)(htf + cg + 4) = p1;
    }
}

// ---------------- output head ----------------
__global__ void out_gemm(const float* __restrict__ Wout, const float* __restrict__ bout, float* __restrict__ out) {
    const int b = blockIdx.x;
    const int wid = threadIdx.x >> 5, lane = threadIdx.x & 31;
    const int o0 = blockIdx.y * 32 + wid * 4;
    const float* __restrict__ h = g_hf[0] + (size_t)b * H_;
    float acc[4] = {0.f, 0.f, 0.f, 0.f};
#pragma unroll
    for (int kk = 0; kk < 8; kk++) {
        int k = kk * 128 + lane * 4;
        float4 hv = *(const float4*)(h + k);
#pragma unroll
        for (int j = 0; j < 4; j++) {
            float4 w = *(const float4*)(Wout + (size_t)(o0 + j) * H_ + k);
            acc[j] += hv.x * w.x + hv.y * w.y + hv.z * w.z + hv.w * w.w;
        }
    }
#pragma unroll
    for (int j = 0; j < 4; j++) {
        float v = acc[j];
#pragma unroll
        for (int s = 16; s > 0; s >>= 1) v += __shfl_xor_sync(0xffffffffu, v, s);
        if (lane == 0) out[(size_t)b * O_ + o0 + j] = v + bout[o0 + j];
    }
}

// ---------------- launch ----------------
extern "C" void kernel_launch(void* const* d_in, const int* in_sizes, int n_in,
                              void* d_out, int out_size) {
    const float* x     = (const float*)d_in[0];
    const float* mask  = (const float*)d_in[1];
    const float* ti    = (const float*)d_in[2];
    const float* W_ih  = (const float*)d_in[3];
    const float* W_hh  = (const float*)d_in[4];
    const float* b_ih  = (const float*)d_in[5];
    const float* b_hh  = (const float*)d_in[6];
    const float* W_out = (const float*)d_in[7];
    const float* b_out = (const float*)d_in[8];
    float* out = (float*)d_out;

    static int smem_set = 0;
    if (!smem_set) {
        cudaFuncSetAttribute(gi_gemm2, cudaFuncAttributeMaxDynamicSharedMemorySize, SMEM_BYTES);
        cudaFuncSetAttribute(gru_step3, cudaFuncAttributeMaxDynamicSharedMemorySize, SMEM_BYTES);
        smem_set = 1;
    }

    // probe gru_step3 at launch index 3 for ncu (outputs overwritten by real t=0)
    {
        size_t total = (size_t)G_ * H_;
        pack_w3<<<(unsigned)((total + 255) / 256), 256>>>(W_hh);          // 0
    }
    zero_h0<<<(B_ * H_ + 255) / 256, 256>>>();                            // 1
    {
        size_t total = (size_t)(T_ * B_) * KIN;
        pack_x<<<(unsigned)((total + 255) / 256), 256>>>(x, mask, ti);    // 2
    }
    gru_step3<<<dim3(B_ / 64, H_ / 32), 512, SMEM_BYTES>>>(0, b_hh);      // 3 (probe)
    {
        size_t total = (size_t)G_ * KIN;
        pack_w<<<(unsigned)((total + 255) / 256), 256>>>(W_ih);           // 4
    }

    gi_gemm2<<<dim3((T_ * B_) / 64, G_ / 96), 256, SMEM_BYTES>>>(b_ih);

    for (int t = 0; t < T_; t++)
        gru_step3<<<dim3(B_ / 64, H_ / 32), 512, SMEM_BYTES>>>(t, b_hh);

    out_gemm<<<dim3(B_, O_ / 32), 256>>>(W_out, b_out, out);
}

// round 7
// speedup vs baseline: 1.6387x; 1.6387x over previous
#include <cuda_runtime.h>
#include <cuda_fp16.h>
#include <cstdint>
#include <math.h>

#define B_   256
#define T_   512
#define D_   128
#define H_   1024
#define G_   3072
#define O_   128
#define DIN  257
#define KIN  320

#define BKS     64
#define SPH     72                     // smem pitch in halves (144B rows)
#define A_HL    (64 * SPH)             // 4608 halves
#define B_HL    (96 * SPH)             // 6912 halves
#define STG_HL  (A_HL + B_HL)          // 11520 halves = 23040 B
#define SMEM_BYTES (4 * STG_HL * 2)    // 92160 B

// ---------------- scratch ----------------
__device__ float  g_gi[(size_t)T_ * B_ * G_];        // gi + b_ih, fp32
__device__ __half g_xh[(size_t)(T_ * B_) * KIN];     // packed inputs fp16
__device__ __half g_wih[(size_t)G_ * KIN];           // W_ih padded fp16
__device__ __half g_w3[(size_t)G_ * H_];             // W_hh fp16
__device__ float  g_hf[2][B_ * H_];                  // h fp32
__device__ __half g_hh[2][B_ * H_];                  // h fp16 (A operand)

// ---------------- helpers ----------------
__device__ __forceinline__ float sigmoidf_(float x) { return 1.0f / (1.0f + expf(-x)); }
__device__ __forceinline__ uint32_t smem_u32(const void* p) {
    uint32_t a; asm("{ .reg .u64 t; cvta.to.shared.u64 t, %1; cvt.u32.u64 %0, t; }" : "=r"(a) : "l"(p)); return a;
}
__device__ __forceinline__ void cpa16(uint32_t d, const void* s) {
    asm volatile("cp.async.cg.shared.global [%0], [%1], 16;" :: "r"(d), "l"(s));
}
__device__ __forceinline__ void cpcommit() { asm volatile("cp.async.commit_group;"); }
__device__ __forceinline__ void cpwait2()  { asm volatile("cp.async.wait_group 2;" ::: "memory"); }
__device__ __forceinline__ void cpwait0()  { asm volatile("cp.async.wait_group 0;" ::: "memory"); }

#define LDSM4(r0, r1, r2, r3, addr) \
    asm volatile("ldmatrix.sync.aligned.m8n8.x4.shared.b16 {%0,%1,%2,%3}, [%4];" \
        : "=r"(r0), "=r"(r1), "=r"(r2), "=r"(r3) : "r"(addr))
#define LDSM2(r0, r1, addr) \
    asm volatile("ldmatrix.sync.aligned.m8n8.x2.shared.b16 {%0,%1}, [%2];" \
        : "=r"(r0), "=r"(r1) : "r"(addr))

__device__ __forceinline__ void mma_f16(float* d, uint32_t a0, uint32_t a1, uint32_t a2, uint32_t a3,
                                        uint32_t b0, uint32_t b1) {
    asm volatile("mma.sync.aligned.m16n8k16.row.col.f32.f16.f16.f32 "
        "{%0,%1,%2,%3},{%4,%5,%6,%7},{%8,%9},{%0,%1,%2,%3};\n"
        : "+f"(d[0]), "+f"(d[1]), "+f"(d[2]), "+f"(d[3])
        : "r"(a0), "r"(a1), "r"(a2), "r"(a3), "r"(b0), "r"(b1));
}

// ---------------- fp16 ldmatrix mainloop: 64M x 96N, BK=64, 256 threads ----------------
// 8 warps (2m x 4n), warp tile 32x24. B = three 32-row gate slices.
template<int NSTG>
__device__ __forceinline__ void mainloop16(
    uint32_t sbase,
    const __half* __restrict__ Ag, int lda,
    const __half* __restrict__ B0, const __half* __restrict__ B1,
    const __half* __restrict__ B2, int ldb,
    int tid, int wm, int wn, float acc[2][3][4])
{
    const int lane = tid & 31;
    // ldmatrix lane address offsets (bytes within a stage buffer)
    const int lrow = lane & 15, lcol = (lane >> 4) << 3;
    const uint32_t aoff = (uint32_t)(((wm + lrow) * SPH + lcol) * 2);
    const int b4row = wn + ((lane >> 4) << 3) + (lane & 7);
    const int bcol = ((lane >> 3) & 1) << 3;
    const uint32_t b4off = (uint32_t)((b4row * SPH + bcol) * 2);
    const int b2row = wn + 16 + (lane & 7);
    const uint32_t b2off = (uint32_t)((b2row * SPH + bcol) * 2);

    auto issue = [&](int s) {
        int buf = s & 3;
        uint32_t ab = sbase + (uint32_t)(buf * STG_HL) * 2u;
        uint32_t bb = ab + A_HL * 2u;
        int kc = s * BKS;
#pragma unroll
        for (int i = 0; i < 2; i++) {        // A: 64 rows x 64 halves = 512 x 16B
            int f = tid + 256 * i, r = f >> 3, c4 = f & 7;
            cpa16(ab + (uint32_t)(r * SPH + c4 * 8) * 2u, Ag + (size_t)r * lda + kc + c4 * 8);
        }
#pragma unroll
        for (int i = 0; i < 3; i++) {        // B: 96 rows x 64 halves = 768 x 16B
            int f = tid + 256 * i, r = f >> 3, c4 = f & 7;
            const __half* base = (r < 32) ? B0 : ((r < 64) ? B1 : B2);
            cpa16(bb + (uint32_t)(r * SPH + c4 * 8) * 2u, base + (size_t)(r & 31) * ldb + kc + c4 * 8);
        }
        cpcommit();
    };

    issue(0); issue(1); issue(2);
#pragma unroll 1
    for (int s = 0; s < NSTG; s++) {
        cpwait2();
        __syncthreads();
        uint32_t ab = sbase + (uint32_t)((s & 3) * STG_HL) * 2u;
        uint32_t bb = ab + A_HL * 2u;
#pragma unroll
        for (int g = 0; g < 4; g++) {        // four k16 groups per BK=64
            const uint32_t gof = (uint32_t)(g * 16 * 2);
            uint32_t A0[4], A1[4], Bb[6];
            LDSM4(A0[0], A0[1], A0[2], A0[3], ab + aoff + gof);
            LDSM4(A1[0], A1[1], A1[2], A1[3], ab + aoff + (uint32_t)(16 * SPH * 2) + gof);
            LDSM4(Bb[0], Bb[1], Bb[2], Bb[3], bb + b4off + gof);
            LDSM2(Bb[4], Bb[5], bb + b2off + gof);
#pragma unroll
            for (int nf = 0; nf < 3; nf++) {
                mma_f16(acc[0][nf], A0[0], A0[1], A0[2], A0[3], Bb[2 * nf], Bb[2 * nf + 1]);
                mma_f16(acc[1][nf], A1[0], A1[1], A1[2], A1[3], Bb[2 * nf], Bb[2 * nf + 1]);
            }
        }
        if (s + 3 < NSTG) issue(s + 3); else cpcommit();
    }
    cpwait0();
    __syncthreads();
}

// ---------------- pack kernels (fp32 -> fp16) ----------------
__global__ void pack_x(const float* __restrict__ x, const float* __restrict__ mask, const float* __restrict__ ti) {
    size_t idx = (size_t)blockIdx.x * blockDim.x + threadIdx.x;
    if (idx >= (size_t)(T_ * B_) * KIN) return;
    int k = (int)(idx % KIN);
    size_t row = idx / KIN;
    int t = (int)(row >> 8), b = (int)(row & 255);
    float v = 0.f;
    if (k < 128) v = x[((size_t)b * T_ + t) * D_ + k];
    else if (k < 256) v = mask[((size_t)b * T_ + t) * D_ + (k - 128)];
    else if (k == 256) v = ti[(size_t)b * T_ + t];
    g_xh[idx] = __float2half_rn(v);
}
__global__ void pack_w(const float* __restrict__ W_ih) {
    size_t idx = (size_t)blockIdx.x * blockDim.x + threadIdx.x;
    if (idx >= (size_t)G_ * KIN) return;
    int k = (int)(idx % KIN); size_t g = idx / KIN;
    g_wih[idx] = (k < DIN) ? __float2half_rn(W_ih[g * DIN + k]) : __float2half_rn(0.0f);
}
__global__ void pack_w3(const float* __restrict__ W_hh) {
    size_t idx = (size_t)blockIdx.x * blockDim.x + threadIdx.x;
    if (idx < (size_t)G_ * H_) g_w3[idx] = __float2half_rn(W_hh[idx]);
}
__global__ void zero_h0() {
    int idx = blockIdx.x * blockDim.x + threadIdx.x;
    if (idx < B_ * H_) { g_hf[0][idx] = 0.0f; g_hh[0][idx] = __float2half_rn(0.0f); }
}

// ---------------- gi GEMM: [131072 x 3072] fp16 ----------------
__global__ __launch_bounds__(256) void gi_gemm3(const float* __restrict__ b_ih) {
    extern __shared__ float smf[];
    uint32_t sbase = smem_u32(smf);
    const int tid = threadIdx.x, lane = tid & 31, wid = tid >> 5;
    const int wm = (wid >> 2) * 32, wn = (wid & 3) * 24;
    const int g4 = lane >> 2, tig = lane & 3;
    const size_t m0 = (size_t)blockIdx.x * 64;
    const int n0 = blockIdx.y * 96;

    float acc[2][3][4];
#pragma unroll
    for (int i = 0; i < 2; i++)
#pragma unroll
        for (int j = 0; j < 3; j++)
#pragma unroll
            for (int e = 0; e < 4; e++) acc[i][j][e] = 0.f;

    mainloop16<KIN / BKS>(sbase, g_xh + m0 * KIN, KIN,
                          g_wih + (size_t)n0 * KIN,
                          g_wih + (size_t)(n0 + 32) * KIN,
                          g_wih + (size_t)(n0 + 64) * KIN, KIN,
                          tid, wm, wn, acc);

#pragma unroll
    for (int mt = 0; mt < 2; mt++)
#pragma unroll
        for (int nf = 0; nf < 3; nf++)
#pragma unroll
            for (int e = 0; e < 4; e++) {
                size_t row = m0 + wm + mt * 16 + g4 + ((e >> 1) << 3);
                int col = n0 + wn + nf * 8 + 2 * tig + (e & 1);
                g_gi[row * G_ + col] = acc[mt][nf][e] + b_ih[col];
            }
}

// ---------------- fused GRU step (fp16) ----------------
__global__ __launch_bounds__(256) void gru_step4(int t, const float* __restrict__ bhh) {
    extern __shared__ float smf[];
    uint32_t sbase = smem_u32(smf);
    const int tid = threadIdx.x, lane = tid & 31, wid = tid >> 5;
    const int wm = (wid >> 2) * 32, wn = (wid & 3) * 24;
    const int g4 = lane >> 2, tig = lane & 3;
    const int m0 = blockIdx.x * 64, n0 = blockIdx.y * 32;

    float acc[2][3][4];
#pragma unroll
    for (int i = 0; i < 2; i++)
#pragma unroll
        for (int j = 0; j < 3; j++)
#pragma unroll
            for (int e = 0; e < 4; e++) acc[i][j][e] = 0.f;

    mainloop16<H_ / BKS>(sbase, g_hh[t & 1] + (size_t)m0 * H_, H_,
                         g_w3 + (size_t)n0 * H_,
                         g_w3 + (size_t)(H_ + n0) * H_,
                         g_w3 + (size_t)(2 * H_ + n0) * H_, H_,
                         tid, wm, wn, acc);

    // acc -> smem gh tile [64][96] pitch 100
    float* gh = smf;
#pragma unroll
    for (int mt = 0; mt < 2; mt++)
#pragma unroll
        for (int nf = 0; nf < 3; nf++)
#pragma unroll
            for (int e = 0; e < 4; e++) {
                int row = wm + mt * 16 + g4 + ((e >> 1) << 3);
                int col = wn + nf * 8 + 2 * tig + (e & 1);
                gh[row * 100 + col] = acc[mt][nf][e];
            }
    __syncthreads();

    // gate math: thread -> (batch row r, h-cols cg..cg+7)
    const int r = tid >> 2;
    const int cg = (tid & 3) * 8;
    const int m = m0 + r;
    const float* __restrict__ gi = g_gi + ((size_t)t * B_ + m) * G_ + n0;
    const float* __restrict__ hp = g_hf[t & 1] + (size_t)m * H_ + n0;
    float* __restrict__ ho  = g_hf[(t + 1) & 1] + (size_t)m * H_ + n0;
    __half* __restrict__ hx = g_hh[(t + 1) & 1] + (size_t)m * H_ + n0;

    float4 ir0 = *(const float4*)(gi + cg),          ir1 = *(const float4*)(gi + cg + 4);
    float4 iz0 = *(const float4*)(gi + H_ + cg),     iz1 = *(const float4*)(gi + H_ + cg + 4);
    float4 in0 = *(const float4*)(gi + 2 * H_ + cg), in1 = *(const float4*)(gi + 2 * H_ + cg + 4);
    float4 hv0 = *(const float4*)(hp + cg),          hv1 = *(const float4*)(hp + cg + 4);
    float irr[8] = {ir0.x, ir0.y, ir0.z, ir0.w, ir1.x, ir1.y, ir1.z, ir1.w};
    float izz[8] = {iz0.x, iz0.y, iz0.z, iz0.w, iz1.x, iz1.y, iz1.z, iz1.w};
    float inn[8] = {in0.x, in0.y, in0.z, in0.w, in1.x, in1.y, in1.z, in1.w};
    float hvv[8] = {hv0.x, hv0.y, hv0.z, hv0.w, hv1.x, hv1.y, hv1.z, hv1.w};
    float o[8];
#pragma unroll
    for (int j = 0; j < 8; j++) {
        int cc = cg + j;
        float rr = sigmoidf_(irr[j] + gh[r * 100 + cc] + bhh[n0 + cc]);
        float zz = sigmoidf_(izz[j] + gh[r * 100 + 32 + cc] + bhh[H_ + n0 + cc]);
        float nn = tanhf(inn[j] + rr * (gh[r * 100 + 64 + cc] + bhh[2 * H_ + n0 + cc]));
        o[j] = (1.0f - zz) * nn + zz * hvv[j];
    }
    float4 w0 = { o[0], o[1], o[2], o[3] };
    float4 w1 = { o[4], o[5], o[6], o[7] };
    *(float4*)(ho + cg) = w0;
    *(float4*)(ho + cg + 4) = w1;
#pragma unroll
    for (int j = 0; j < 4; j++)
        *(__half2*)(hx + cg + 2 * j) = __floats2half2_rn(o[2 * j], o[2 * j + 1]);
}

// ---------------- output head ----------------
__global__ void out_gemm(const float* __restrict__ Wout, const float* __restrict__ bout, float* __restrict__ out) {
    const int b = blockIdx.x;
    const int wid = threadIdx.x >> 5, lane = threadIdx.x & 31;
    const int o0 = blockIdx.y * 32 + wid * 4;
    const float* __restrict__ h = g_hf[0] + (size_t)b * H_;
    float acc[4] = {0.f, 0.f, 0.f, 0.f};
#pragma unroll
    for (int kk = 0; kk < 8; kk++) {
        int k = kk * 128 + lane * 4;
        float4 hv = *(const float4*)(h + k);
#pragma unroll
        for (int j = 0; j < 4; j++) {
            float4 w = *(const float4*)(Wout + (size_t)(o0 + j) * H_ + k);
            acc[j] += hv.x * w.x + hv.y * w.y + hv.z * w.z + hv.w * w.w;
        }
    }
#pragma unroll
    for (int j = 0; j < 4; j++) {
        float v = acc[j];
#pragma unroll
        for (int s = 16; s > 0; s >>= 1) v += __shfl_xor_sync(0xffffffffu, v, s);
        if (lane == 0) out[(size_t)b * O_ + o0 + j] = v + bout[o0 + j];
    }
}

// ---------------- launch ----------------
extern "C" void kernel_launch(void* const* d_in, const int* in_sizes, int n_in,
                              void* d_out, int out_size) {
    const float* x     = (const float*)d_in[0];
    const float* mask  = (const float*)d_in[1];
    const float* ti    = (const float*)d_in[2];
    const float* W_ih  = (const float*)d_in[3];
    const float* W_hh  = (const float*)d_in[4];
    const float* b_ih  = (const float*)d_in[5];
    const float* b_hh  = (const float*)d_in[6];
    const float* W_out = (const float*)d_in[7];
    const float* b_out = (const float*)d_in[8];
    float* out = (float*)d_out;

    static int smem_set = 0;
    if (!smem_set) {
        cudaFuncSetAttribute(gi_gemm3, cudaFuncAttributeMaxDynamicSharedMemorySize, SMEM_BYTES);
        cudaFuncSetAttribute(gru_step4, cudaFuncAttributeMaxDynamicSharedMemorySize, SMEM_BYTES);
        smem_set = 1;
    }

    // probe gru_step4 at launch index 3 for ncu (outputs fully overwritten by real t=0)
    {
        size_t total = (size_t)G_ * H_;
        pack_w3<<<(unsigned)((total + 255) / 256), 256>>>(W_hh);          // 0
    }
    zero_h0<<<(B_ * H_ + 255) / 256, 256>>>();                            // 1
    {
        size_t total = (size_t)(T_ * B_) * KIN;
        pack_x<<<(unsigned)((total + 255) / 256), 256>>>(x, mask, ti);    // 2
    }
    gru_step4<<<dim3(B_ / 64, H_ / 32), 256, SMEM_BYTES>>>(0, b_hh);      // 3 (probe)
    {
        size_t total = (size_t)G_ * KIN;
        pack_w<<<(unsigned)((total + 255) / 256), 256>>>(W_ih);           // 4
    }

    gi_gemm3<<<dim3((T_ * B_) / 64, G_ / 96), 256, SMEM_BYTES>>>(b_ih);

    for (int t = 0; t < T_; t++)
        gru_step4<<<dim3(B_ / 64, H_ / 32), 256, SMEM_BYTES>>>(t, b_hh);

    out_gemm<<<dim3(B_, O_ / 32), 256>>>(W_out, b_out, out);
}

// round 8
// speedup vs baseline: 1.9135x; 1.1677x over previous
#include <cuda_runtime.h>
#include <cuda_fp16.h>
#include <cstdint>
#include <math.h>

#define B_   256
#define T_   512
#define D_   128
#define H_   1024
#define G_   3072
#define O_   128
#define DIN  257
#define KIN  320

// ---- gi GEMM tiling (fp16, ldmatrix, cp.async) ----
#define BKS     64
#define SPH     72
#define A_HL    (64 * SPH)
#define B_HL    (96 * SPH)
#define STG_HL  (A_HL + B_HL)
#define GI_SMEM (4 * STG_HL * 2)

// ---- persistent step kernel smem ----
#define WCH     12288                    // one k-chunk: 96 rows x 128B
#define W_SM    (16 * WCH)               // 196608
#define AST     8192                     // A stage: 64 rows x 128B
#define P_SMEM  (W_SM + 4 * AST)         // 229376

// ---------------- scratch ----------------
__device__ float  g_gi[(size_t)T_ * B_ * G_];
__device__ __half g_xh[(size_t)(T_ * B_) * KIN];
__device__ __half g_wih[(size_t)G_ * KIN];
__device__ __half g_w3[(size_t)G_ * H_];
__device__ float  g_hf[2][B_ * H_];
__device__ __half g_hh[2][B_ * H_];
__device__ unsigned g_bar;

// ---------------- helpers ----------------
__device__ __forceinline__ float sigmoidf_(float x) { return 1.0f / (1.0f + expf(-x)); }
__device__ __forceinline__ uint32_t smem_u32(const void* p) {
    uint32_t a; asm("{ .reg .u64 t; cvta.to.shared.u64 t, %1; cvt.u32.u64 %0, t; }" : "=r"(a) : "l"(p)); return a;
}
__device__ __forceinline__ void cpa16(uint32_t d, const void* s) {
    asm volatile("cp.async.cg.shared.global [%0], [%1], 16;" :: "r"(d), "l"(s));
}
__device__ __forceinline__ void cpcommit() { asm volatile("cp.async.commit_group;"); }
__device__ __forceinline__ void cpwait2()  { asm volatile("cp.async.wait_group 2;" ::: "memory"); }
__device__ __forceinline__ void cpwait0()  { asm volatile("cp.async.wait_group 0;" ::: "memory"); }

#define LDSM4(r0, r1, r2, r3, addr) \
    asm volatile("ldmatrix.sync.aligned.m8n8.x4.shared.b16 {%0,%1,%2,%3}, [%4];" \
        : "=r"(r0), "=r"(r1), "=r"(r2), "=r"(r3) : "r"(addr))
#define LDSM2(r0, r1, addr) \
    asm volatile("ldmatrix.sync.aligned.m8n8.x2.shared.b16 {%0,%1}, [%2];" \
        : "=r"(r0), "=r"(r1) : "r"(addr))

__device__ __forceinline__ void mma_f16(float* d, uint32_t a0, uint32_t a1, uint32_t a2, uint32_t a3,
                                        uint32_t b0, uint32_t b1) {
    asm volatile("mma.sync.aligned.m16n8k16.row.col.f32.f16.f16.f32 "
        "{%0,%1,%2,%3},{%4,%5,%6,%7},{%8,%9},{%0,%1,%2,%3};\n"
        : "+f"(d[0]), "+f"(d[1]), "+f"(d[2]), "+f"(d[3])
        : "r"(a0), "r"(a1), "r"(a2), "r"(a3), "r"(b0), "r"(b1));
}

// ---------------- gi GEMM mainloop (round-7, unchanged) ----------------
template<int NSTG>
__device__ __forceinline__ void mainloop16(
    uint32_t sbase,
    const __half* __restrict__ Ag, int lda,
    const __half* __restrict__ B0, const __half* __restrict__ B1,
    const __half* __restrict__ B2, int ldb,
    int tid, int wm, int wn, float acc[2][3][4])
{
    const int lane = tid & 31;
    const int lrow = lane & 15, lcol = (lane >> 4) << 3;
    const uint32_t aoff = (uint32_t)(((wm + lrow) * SPH + lcol) * 2);
    const int b4row = wn + ((lane >> 4) << 3) + (lane & 7);
    const int bcol = ((lane >> 3) & 1) << 3;
    const uint32_t b4off = (uint32_t)((b4row * SPH + bcol) * 2);
    const int b2row = wn + 16 + (lane & 7);
    const uint32_t b2off = (uint32_t)((b2row * SPH + bcol) * 2);

    auto issue = [&](int s) {
        int buf = s & 3;
        uint32_t ab = sbase + (uint32_t)(buf * STG_HL) * 2u;
        uint32_t bb = ab + A_HL * 2u;
        int kc = s * BKS;
#pragma unroll
        for (int i = 0; i < 2; i++) {
            int f = tid + 256 * i, r = f >> 3, c4 = f & 7;
            cpa16(ab + (uint32_t)(r * SPH + c4 * 8) * 2u, Ag + (size_t)r * lda + kc + c4 * 8);
        }
#pragma unroll
        for (int i = 0; i < 3; i++) {
            int f = tid + 256 * i, r = f >> 3, c4 = f & 7;
            const __half* base = (r < 32) ? B0 : ((r < 64) ? B1 : B2);
            cpa16(bb + (uint32_t)(r * SPH + c4 * 8) * 2u, base + (size_t)(r & 31) * ldb + kc + c4 * 8);
        }
        cpcommit();
    };

    issue(0); issue(1); issue(2);
#pragma unroll 1
    for (int s = 0; s < NSTG; s++) {
        cpwait2();
        __syncthreads();
        uint32_t ab = sbase + (uint32_t)((s & 3) * STG_HL) * 2u;
        uint32_t bb = ab + A_HL * 2u;
#pragma unroll
        for (int g = 0; g < 4; g++) {
            const uint32_t gof = (uint32_t)(g * 16 * 2);
            uint32_t A0[4], A1[4], Bb[6];
            LDSM4(A0[0], A0[1], A0[2], A0[3], ab + aoff + gof);
            LDSM4(A1[0], A1[1], A1[2], A1[3], ab + aoff + (uint32_t)(16 * SPH * 2) + gof);
            LDSM4(Bb[0], Bb[1], Bb[2], Bb[3], bb + b4off + gof);
            LDSM2(Bb[4], Bb[5], bb + b2off + gof);
#pragma unroll
            for (int nf = 0; nf < 3; nf++) {
                mma_f16(acc[0][nf], A0[0], A0[1], A0[2], A0[3], Bb[2 * nf], Bb[2 * nf + 1]);
                mma_f16(acc[1][nf], A1[0], A1[1], A1[2], A1[3], Bb[2 * nf], Bb[2 * nf + 1]);
            }
        }
        if (s + 3 < NSTG) issue(s + 3); else cpcommit();
    }
    cpwait0();
    __syncthreads();
}

// ---------------- pack kernels ----------------
__global__ void pack_x(const float* __restrict__ x, const float* __restrict__ mask, const float* __restrict__ ti) {
    size_t idx = (size_t)blockIdx.x * blockDim.x + threadIdx.x;
    if (idx >= (size_t)(T_ * B_) * KIN) return;
    int k = (int)(idx % KIN);
    size_t row = idx / KIN;
    int t = (int)(row >> 8), b = (int)(row & 255);
    float v = 0.f;
    if (k < 128) v = x[((size_t)b * T_ + t) * D_ + k];
    else if (k < 256) v = mask[((size_t)b * T_ + t) * D_ + (k - 128)];
    else if (k == 256) v = ti[(size_t)b * T_ + t];
    g_xh[idx] = __float2half_rn(v);
}
__global__ void pack_w(const float* __restrict__ W_ih) {
    size_t idx = (size_t)blockIdx.x * blockDim.x + threadIdx.x;
    if (idx >= (size_t)G_ * KIN) return;
    int k = (int)(idx % KIN); size_t g = idx / KIN;
    g_wih[idx] = (k < DIN) ? __float2half_rn(W_ih[g * DIN + k]) : __float2half_rn(0.0f);
}
__global__ void pack_w3(const float* __restrict__ W_hh) {
    size_t idx = (size_t)blockIdx.x * blockDim.x + threadIdx.x;
    if (idx < (size_t)G_ * H_) g_w3[idx] = __float2half_rn(W_hh[idx]);
}
__global__ void zero_h0() {
    int idx = blockIdx.x * blockDim.x + threadIdx.x;
    if (idx == 0) g_bar = 0u;
    if (idx < B_ * H_) { g_hf[0][idx] = 0.0f; g_hh[0][idx] = __float2half_rn(0.0f); }
}

// ---------------- gi GEMM ----------------
__global__ __launch_bounds__(256) void gi_gemm3(const float* __restrict__ b_ih) {
    extern __shared__ float smf[];
    uint32_t sbase = smem_u32(smf);
    const int tid = threadIdx.x, lane = tid & 31, wid = tid >> 5;
    const int wm = (wid >> 2) * 32, wn = (wid & 3) * 24;
    const int g4 = lane >> 2, tig = lane & 3;
    const size_t m0 = (size_t)blockIdx.x * 64;
    const int n0 = blockIdx.y * 96;

    float acc[2][3][4];
#pragma unroll
    for (int i = 0; i < 2; i++)
#pragma unroll
        for (int j = 0; j < 3; j++)
#pragma unroll
            for (int e = 0; e < 4; e++) acc[i][j][e] = 0.f;

    mainloop16<KIN / BKS>(sbase, g_xh + m0 * KIN, KIN,
                          g_wih + (size_t)n0 * KIN,
                          g_wih + (size_t)(n0 + 32) * KIN,
                          g_wih + (size_t)(n0 + 64) * KIN, KIN,
                          tid, wm, wn, acc);

#pragma unroll
    for (int mt = 0; mt < 2; mt++)
#pragma unroll
        for (int nf = 0; nf < 3; nf++)
#pragma unroll
            for (int e = 0; e < 4; e++) {
                size_t row = m0 + wm + mt * 16 + g4 + ((e >> 1) << 3);
                int col = n0 + wn + nf * 8 + 2 * tig + (e & 1);
                g_gi[row * G_ + col] = acc[mt][nf][e] + b_ih[col];
            }
}

// ---------------- persistent GRU recurrence ----------------
// 128 CTAs (all co-resident), each owns m-slice 64 x n-slice 32 (x3 gates).
// W slice (96x1024 fp16) resident in SMEM, swizzled 128B rows. h streamed per step.
__global__ __launch_bounds__(256, 1) void gru_persist(const float* __restrict__ bhh) {
    extern __shared__ char smc[];
    uint32_t sb = smem_u32(smc);            // W chunks base
    uint32_t ast = sb + W_SM;               // A staging (4 x 8192), also gh tile
    float* gh = (float*)(smc + W_SM);
    const int tid = threadIdx.x, lane = tid & 31, wid = tid >> 5;
    const int wm = (wid >> 2) * 32, wn = (wid & 3) * 24;
    const int m0 = (blockIdx.x >> 5) * 64;
    const int n0 = (blockIdx.x & 31) * 32;

    // ---- load W slice into smem once (swizzled) ----
    {
        const __half* Wg = g_w3;
#pragma unroll 1
        for (int i = tid; i < 12288; i += 256) {          // 16B chunks
            int rr = i >> 7, cg = i & 127;                // row 0..95, col-group 0..127
            int s = cg >> 3, c = cg & 7;
            int grow = (rr >> 5) * H_ + n0 + (rr & 31);
            uint32_t dst = sb + (uint32_t)(s * WCH + rr * 128 + ((c ^ (rr & 7)) << 4));
            cpa16(dst, Wg + (size_t)grow * H_ + s * 64 + c * 8);
        }
        cpcommit(); cpwait0();
        __syncthreads();
    }

    // ldmatrix lane constants
    const int arow0 = wm + (lane & 15);                   // + mt*16
    const int acsel = (lane >> 4);                        // 0/1
    const int b4row = wn + ((lane >> 4) << 3) + (lane & 7);
    const int b2row = wn + 16 + (lane & 7);
    const int bcsel = (lane >> 3) & 1;

    // epilogue thread mapping
    const int er = tid >> 2, ecg = (tid & 3) * 8;
    const int em = m0 + er;

#pragma unroll 1
    for (int t = 0; t < T_; t++) {
        // gi prefetch (independent of barrier)
        const float* __restrict__ gi = g_gi + ((size_t)t * B_ + em) * G_ + n0;
        float4 ir0 = *(const float4*)(gi + ecg),          ir1 = *(const float4*)(gi + ecg + 4);
        float4 iz0 = *(const float4*)(gi + H_ + ecg),     iz1 = *(const float4*)(gi + H_ + ecg + 4);
        float4 in0 = *(const float4*)(gi + 2 * H_ + ecg), in1 = *(const float4*)(gi + 2 * H_ + ecg + 4);

        // ---- grid barrier: wait until all CTAs finished writing h(t) ----
        __syncthreads();
        if (tid == 0) {
            __threadfence();
            asm volatile("red.release.gpu.global.add.u32 [%0], 1;" :: "l"(&g_bar) : "memory");
            unsigned v; const unsigned tgt = 128u * (unsigned)(t + 1);
            do { asm volatile("ld.acquire.gpu.global.u32 %0, [%1];" : "=r"(v) : "l"(&g_bar)); } while (v < tgt);
        }
        __syncthreads();

        const __half* __restrict__ Ah = g_hh[t & 1] + (size_t)m0 * H_;
        const float* __restrict__ hp = g_hf[t & 1] + (size_t)em * H_ + n0;
        float4 hv0 = *(const float4*)(hp + ecg), hv1 = *(const float4*)(hp + ecg + 4);

        float acc[2][3][4];
#pragma unroll
        for (int i = 0; i < 2; i++)
#pragma unroll
            for (int j = 0; j < 3; j++)
#pragma unroll
                for (int e = 0; e < 4; e++) acc[i][j][e] = 0.f;

        // ---- A pipeline: 16 stages of BK=64 halves ----
        auto issueA = [&](int s) {
            int buf = s & 3;
            uint32_t ab = ast + (uint32_t)(buf * AST);
            int kc = s * 64;
#pragma unroll
            for (int i = 0; i < 2; i++) {
                int f = tid + 256 * i, r = f >> 3, c = f & 7;
                cpa16(ab + (uint32_t)(r * 128 + ((c ^ (r & 7)) << 4)),
                      Ah + (size_t)r * H_ + kc + c * 8);
            }
            cpcommit();
        };
        issueA(0); issueA(1); issueA(2);
#pragma unroll 1
        for (int s = 0; s < 16; s++) {
            cpwait2();
            __syncthreads();
            uint32_t ab = ast + (uint32_t)((s & 3) * AST);
            uint32_t wb = sb + (uint32_t)(s * WCH);
#pragma unroll
            for (int g = 0; g < 4; g++) {
                uint32_t A0[4], A1[4], Bb[6];
                {
                    int c = 2 * g + acsel;
                    int r0 = arow0, r1 = arow0 + 16;
                    LDSM4(A0[0], A0[1], A0[2], A0[3], ab + (uint32_t)(r0 * 128 + ((c ^ (r0 & 7)) << 4)));
                    LDSM4(A1[0], A1[1], A1[2], A1[3], ab + (uint32_t)(r1 * 128 + ((c ^ (r1 & 7)) << 4)));
                }
                {
                    int c = 2 * g + bcsel;
                    LDSM4(Bb[0], Bb[1], Bb[2], Bb[3], wb + (uint32_t)(b4row * 128 + ((c ^ (b4row & 7)) << 4)));
                    LDSM2(Bb[4], Bb[5], wb + (uint32_t)(b2row * 128 + ((c ^ (b2row & 7)) << 4)));
                }
#pragma unroll
                for (int nf = 0; nf < 3; nf++) {
                    mma_f16(acc[0][nf], A0[0], A0[1], A0[2], A0[3], Bb[2 * nf], Bb[2 * nf + 1]);
                    mma_f16(acc[1][nf], A1[0], A1[1], A1[2], A1[3], Bb[2 * nf], Bb[2 * nf + 1]);
                }
            }
            if (s + 3 < 16) issueA(s + 3); else cpcommit();
        }
        cpwait0();
        __syncthreads();   // A staging free -> reuse as gh tile

        // ---- acc -> gh smem [64][96] pitch 100 ----
        {
            const int g4 = lane >> 2, tig = lane & 3;
#pragma unroll
            for (int mt = 0; mt < 2; mt++)
#pragma unroll
                for (int nf = 0; nf < 3; nf++)
#pragma unroll
                    for (int e = 0; e < 4; e++) {
                        int row = wm + mt * 16 + g4 + ((e >> 1) << 3);
                        int col = wn + nf * 8 + 2 * tig + (e & 1);
                        gh[row * 100 + col] = acc[mt][nf][e];
                    }
        }
        __syncthreads();

        // ---- gate math ----
        {
            float* __restrict__ ho  = g_hf[(t + 1) & 1] + (size_t)em * H_ + n0;
            __half* __restrict__ hx = g_hh[(t + 1) & 1] + (size_t)em * H_ + n0;
            float irr[8] = {ir0.x, ir0.y, ir0.z, ir0.w, ir1.x, ir1.y, ir1.z, ir1.w};
            float izz[8] = {iz0.x, iz0.y, iz0.z, iz0.w, iz1.x, iz1.y, iz1.z, iz1.w};
            float inn[8] = {in0.x, in0.y, in0.z, in0.w, in1.x, in1.y, in1.z, in1.w};
            float hvv[8] = {hv0.x, hv0.y, hv0.z, hv0.w, hv1.x, hv1.y, hv1.z, hv1.w};
            float o[8];
#pragma unroll
            for (int j = 0; j < 8; j++) {
                int cc = ecg + j;
                float rr = sigmoidf_(irr[j] + gh[er * 100 + cc] + bhh[n0 + cc]);
                float zz = sigmoidf_(izz[j] + gh[er * 100 + 32 + cc] + bhh[H_ + n0 + cc]);
                float nn = tanhf(inn[j] + rr * (gh[er * 100 + 64 + cc] + bhh[2 * H_ + n0 + cc]));
                o[j] = (1.0f - zz) * nn + zz * hvv[j];
            }
            float4 w0 = { o[0], o[1], o[2], o[3] };
            float4 w1 = { o[4], o[5], o[6], o[7] };
            *(float4*)(ho + ecg) = w0;
            *(float4*)(ho + ecg + 4) = w1;
#pragma unroll
            for (int j = 0; j < 4; j++)
                *(__half2*)(hx + ecg + 2 * j) = __floats2half2_rn(o[2 * j], o[2 * j + 1]);
        }
        __syncthreads();   // gh tile reuse safety before next iteration's staging
    }
}

// ---------------- output head ----------------
__global__ void out_gemm(const float* __restrict__ Wout, const float* __restrict__ bout, float* __restrict__ out) {
    const int b = blockIdx.x;
    const int wid = threadIdx.x >> 5, lane = threadIdx.x & 31;
    const int o0 = blockIdx.y * 32 + wid * 4;
    const float* __restrict__ h = g_hf[0] + (size_t)b * H_;
    float acc[4] = {0.f, 0.f, 0.f, 0.f};
#pragma unroll
    for (int kk = 0; kk < 8; kk++) {
        int k = kk * 128 + lane * 4;
        float4 hv = *(const float4*)(h + k);
#pragma unroll
        for (int j = 0; j < 4; j++) {
            float4 w = *(const float4*)(Wout + (size_t)(o0 + j) * H_ + k);
            acc[j] += hv.x * w.x + hv.y * w.y + hv.z * w.z + hv.w * w.w;
        }
    }
#pragma unroll
    for (int j = 0; j < 4; j++) {
        float v = acc[j];
#pragma unroll
        for (int s = 16; s > 0; s >>= 1) v += __shfl_xor_sync(0xffffffffu, v, s);
        if (lane == 0) out[(size_t)b * O_ + o0 + j] = v + bout[o0 + j];
    }
}

// ---------------- launch ----------------
extern "C" void kernel_launch(void* const* d_in, const int* in_sizes, int n_in,
                              void* d_out, int out_size) {
    const float* x     = (const float*)d_in[0];
    const float* mask  = (const float*)d_in[1];
    const float* ti    = (const float*)d_in[2];
    const float* W_ih  = (const float*)d_in[3];
    const float* W_hh  = (const float*)d_in[4];
    const float* b_ih  = (const float*)d_in[5];
    const float* b_hh  = (const float*)d_in[6];
    const float* W_out = (const float*)d_in[7];
    const float* b_out = (const float*)d_in[8];
    float* out = (float*)d_out;

    static int smem_set = 0;
    if (!smem_set) {
        cudaFuncSetAttribute(gi_gemm3, cudaFuncAttributeMaxDynamicSharedMemorySize, GI_SMEM);
        cudaFuncSetAttribute(gru_persist, cudaFuncAttributeMaxDynamicSharedMemorySize, P_SMEM);
        smem_set = 1;
    }

    {
        size_t total = (size_t)G_ * H_;
        pack_w3<<<(unsigned)((total + 255) / 256), 256>>>(W_hh);          // 0
    }
    zero_h0<<<(B_ * H_ + 255) / 256, 256>>>();                            // 1 (also g_bar=0)
    {
        size_t total = (size_t)(T_ * B_) * KIN;
        pack_x<<<(unsigned)((total + 255) / 256), 256>>>(x, mask, ti);    // 2
    }
    {
        size_t total = (size_t)G_ * KIN;
        pack_w<<<(unsigned)((total + 255) / 256), 256>>>(W_ih);           // 3
    }
    gi_gemm3<<<dim3((T_ * B_) / 64, G_ / 96), 256, GI_SMEM>>>(b_ih);      // 4
    gru_persist<<<128, 256, P_SMEM>>>(b_hh);                              // 5 (ncu -s 5 target)
    out_gemm<<<dim3(B_, O_ / 32), 256>>>(W_out, b_out, out);              // 6
}

// round 9
// speedup vs baseline: 2.0831x; 1.0886x over previous
#include <cuda_runtime.h>
#include <cuda_fp16.h>
#include <cstdint>
#include <math.h>

#define B_   256
#define T_   512
#define D_   128
#define H_   1024
#define G_   3072
#define O_   128
#define DIN  257
#define KIN  320

// ---- gi GEMM tiling ----
#define BKS     64
#define SPH     72
#define A_HL    (64 * SPH)
#define B_HL    (96 * SPH)
#define STG_HL  (A_HL + B_HL)
#define GI_SMEM (4 * STG_HL * 2)

// ---- persistent kernel smem ----
#define WCH     12288                    // one k16x4-chunk of W: 96 rows x 128B
#define W_SM    (16 * WCH)               // 196608
#define AST     8192                     // A stage: 64 rows x 128B
#define P_SMEM  (W_SM + 4 * AST)         // 229376

// ---------------- scratch ----------------
__device__ float  g_gi[(size_t)T_ * B_ * G_];
__device__ __half g_xh[(size_t)(T_ * B_) * KIN];
__device__ __half g_wih[(size_t)G_ * KIN];
__device__ __half g_w3[(size_t)G_ * H_];
__device__ float  g_hf[2][B_ * H_];
__device__ __half g_hh[2][B_ * H_];
__device__ unsigned g_bars[64];          // 4 group counters, stride 16 words

// ---------------- helpers ----------------
__device__ __forceinline__ float sigmoidf_(float x) { return 1.0f / (1.0f + expf(-x)); }
__device__ __forceinline__ uint32_t smem_u32(const void* p) {
    uint32_t a; asm("{ .reg .u64 t; cvta.to.shared.u64 t, %1; cvt.u32.u64 %0, t; }" : "=r"(a) : "l"(p)); return a;
}
__device__ __forceinline__ void cpa16(uint32_t d, const void* s) {
    asm volatile("cp.async.cg.shared.global [%0], [%1], 16;" :: "r"(d), "l"(s));
}
__device__ __forceinline__ void cpcommit() { asm volatile("cp.async.commit_group;"); }
__device__ __forceinline__ void cpwait2()  { asm volatile("cp.async.wait_group 2;" ::: "memory"); }
__device__ __forceinline__ void cpwait0()  { asm volatile("cp.async.wait_group 0;" ::: "memory"); }

#define LDSM4(r0, r1, r2, r3, addr) \
    asm volatile("ldmatrix.sync.aligned.m8n8.x4.shared.b16 {%0,%1,%2,%3}, [%4];" \
        : "=r"(r0), "=r"(r1), "=r"(r2), "=r"(r3) : "r"(addr))
#define LDSM2(r0, r1, addr) \
    asm volatile("ldmatrix.sync.aligned.m8n8.x2.shared.b16 {%0,%1}, [%2];" \
        : "=r"(r0), "=r"(r1) : "r"(addr))

__device__ __forceinline__ void mma_f16(float* d, uint32_t a0, uint32_t a1, uint32_t a2, uint32_t a3,
                                        uint32_t b0, uint32_t b1) {
    asm volatile("mma.sync.aligned.m16n8k16.row.col.f32.f16.f16.f32 "
        "{%0,%1,%2,%3},{%4,%5,%6,%7},{%8,%9},{%0,%1,%2,%3};\n"
        : "+f"(d[0]), "+f"(d[1]), "+f"(d[2]), "+f"(d[3])
        : "r"(a0), "r"(a1), "r"(a2), "r"(a3), "r"(b0), "r"(b1));
}

// ---------------- gi GEMM mainloop (round-7 proven, unchanged) ----------------
template<int NSTG>
__device__ __forceinline__ void mainloop16(
    uint32_t sbase,
    const __half* __restrict__ Ag, int lda,
    const __half* __restrict__ B0, const __half* __restrict__ B1,
    const __half* __restrict__ B2, int ldb,
    int tid, int wm, int wn, float acc[2][3][4])
{
    const int lane = tid & 31;
    const int lrow = lane & 15, lcol = (lane >> 4) << 3;
    const uint32_t aoff = (uint32_t)(((wm + lrow) * SPH + lcol) * 2);
    const int b4row = wn + ((lane >> 4) << 3) + (lane & 7);
    const int bcol = ((lane >> 3) & 1) << 3;
    const uint32_t b4off = (uint32_t)((b4row * SPH + bcol) * 2);
    const int b2row = wn + 16 + (lane & 7);
    const uint32_t b2off = (uint32_t)((b2row * SPH + bcol) * 2);

    auto issue = [&](int s) {
        int buf = s & 3;
        uint32_t ab = sbase + (uint32_t)(buf * STG_HL) * 2u;
        uint32_t bb = ab + A_HL * 2u;
        int kc = s * BKS;
#pragma unroll
        for (int i = 0; i < 2; i++) {
            int f = tid + 256 * i, r = f >> 3, c4 = f & 7;
            cpa16(ab + (uint32_t)(r * SPH + c4 * 8) * 2u, Ag + (size_t)r * lda + kc + c4 * 8);
        }
#pragma unroll
        for (int i = 0; i < 3; i++) {
            int f = tid + 256 * i, r = f >> 3, c4 = f & 7;
            const __half* base = (r < 32) ? B0 : ((r < 64) ? B1 : B2);
            cpa16(bb + (uint32_t)(r * SPH + c4 * 8) * 2u, base + (size_t)(r & 31) * ldb + kc + c4 * 8);
        }
        cpcommit();
    };

    issue(0); issue(1); issue(2);
#pragma unroll 1
    for (int s = 0; s < NSTG; s++) {
        cpwait2();
        __syncthreads();
        uint32_t ab = sbase + (uint32_t)((s & 3) * STG_HL) * 2u;
        uint32_t bb = ab + A_HL * 2u;
#pragma unroll
        for (int g = 0; g < 4; g++) {
            const uint32_t gof = (uint32_t)(g * 16 * 2);
            uint32_t A0[4], A1[4], Bb[6];
            LDSM4(A0[0], A0[1], A0[2], A0[3], ab + aoff + gof);
            LDSM4(A1[0], A1[1], A1[2], A1[3], ab + aoff + (uint32_t)(16 * SPH * 2) + gof);
            LDSM4(Bb[0], Bb[1], Bb[2], Bb[3], bb + b4off + gof);
            LDSM2(Bb[4], Bb[5], bb + b2off + gof);
#pragma unroll
            for (int nf = 0; nf < 3; nf++) {
                mma_f16(acc[0][nf], A0[0], A0[1], A0[2], A0[3], Bb[2 * nf], Bb[2 * nf + 1]);
                mma_f16(acc[1][nf], A1[0], A1[1], A1[2], A1[3], Bb[2 * nf], Bb[2 * nf + 1]);
            }
        }
        if (s + 3 < NSTG) issue(s + 3); else cpcommit();
    }
    cpwait0();
    __syncthreads();
}

// ---------------- fused pack kernel (one launch) ----------------
#define NBX  163840   // pack_x blocks
#define NBW3 12288
#define NBW  3840
#define NBZ  1024
__global__ void pack_fused(const float* __restrict__ x, const float* __restrict__ mask,
                           const float* __restrict__ ti, const float* __restrict__ W_ih,
                           const float* __restrict__ W_hh) {
    long long bid = blockIdx.x;
    int tidl = threadIdx.x;
    if (bid < NBX) {
        size_t idx = (size_t)bid * 256 + tidl;
        int k = (int)(idx % KIN);
        size_t row = idx / KIN;
        int t = (int)(row >> 8), b = (int)(row & 255);
        float v = 0.f;
        if (k < 128) v = x[((size_t)b * T_ + t) * D_ + k];
        else if (k < 256) v = mask[((size_t)b * T_ + t) * D_ + (k - 128)];
        else if (k == 256) v = ti[(size_t)b * T_ + t];
        g_xh[idx] = __float2half_rn(v);
    } else if (bid < NBX + NBW3) {
        size_t idx = (size_t)(bid - NBX) * 256 + tidl;
        g_w3[idx] = __float2half_rn(W_hh[idx]);
    } else if (bid < NBX + NBW3 + NBW) {
        size_t idx = (size_t)(bid - NBX - NBW3) * 256 + tidl;
        int k = (int)(idx % KIN); size_t g = idx / KIN;
        g_wih[idx] = (k < DIN) ? __float2half_rn(W_ih[g * DIN + k]) : __float2half_rn(0.0f);
    } else {
        size_t idx = (size_t)(bid - NBX - NBW3 - NBW) * 256 + tidl;
        if (idx < B_ * H_) { g_hf[0][idx] = 0.0f; g_hh[0][idx] = __float2half_rn(0.0f); }
        if (idx < 64) g_bars[idx] = 0u;
    }
}
__global__ void bar_zero() { if (threadIdx.x < 64) g_bars[threadIdx.x] = 0u; }

// ---------------- gi GEMM ----------------
__global__ __launch_bounds__(256) void gi_gemm3(const float* __restrict__ b_ih) {
    extern __shared__ float smf[];
    uint32_t sbase = smem_u32(smf);
    const int tid = threadIdx.x, lane = tid & 31, wid = tid >> 5;
    const int wm = (wid >> 2) * 32, wn = (wid & 3) * 24;
    const int g4 = lane >> 2, tig = lane & 3;
    const size_t m0 = (size_t)blockIdx.x * 64;
    const int n0 = blockIdx.y * 96;

    float acc[2][3][4];
#pragma unroll
    for (int i = 0; i < 2; i++)
#pragma unroll
        for (int j = 0; j < 3; j++)
#pragma unroll
            for (int e = 0; e < 4; e++) acc[i][j][e] = 0.f;

    mainloop16<KIN / BKS>(sbase, g_xh + m0 * KIN, KIN,
                          g_wih + (size_t)n0 * KIN,
                          g_wih + (size_t)(n0 + 32) * KIN,
                          g_wih + (size_t)(n0 + 64) * KIN, KIN,
                          tid, wm, wn, acc);

#pragma unroll
    for (int mt = 0; mt < 2; mt++)
#pragma unroll
        for (int nf = 0; nf < 3; nf++)
#pragma unroll
            for (int e = 0; e < 4; e++) {
                size_t row = m0 + wm + mt * 16 + g4 + ((e >> 1) << 3);
                int col = n0 + wn + nf * 8 + 2 * tig + (e & 1);
                g_gi[row * G_ + col] = acc[mt][nf][e] + b_ih[col];
            }
}

// ---------------- persistent GRU recurrence (group barriers + register epilogue) ----------------
// 128 CTAs = 4 independent groups of 32 (group = m-slice). W slice resident in SMEM.
// Warp n-tile = 8 cols x 3 gates; each thread owns r/z/n acc for the same (row,col) set.
__global__ __launch_bounds__(256, 1) void gru_persist(const float* __restrict__ bhh) {
    extern __shared__ char smc[];
    uint32_t sb = smem_u32(smc);
    uint32_t ast = sb + W_SM;
    const int tid = threadIdx.x, lane = tid & 31, wid = tid >> 5;
    const int wm = (wid >> 2) * 32;            // 2 m-warp-groups x 32 rows
    const int wn8 = (wid & 3) * 8;             // 4 n-warp-groups x 8 cols
    const int g4 = lane >> 2, tig = lane & 3;
    const int mi = blockIdx.x >> 5, ni = blockIdx.x & 31;
    const int m0 = mi * 64, n0 = ni * 32;
    unsigned* barp = &g_bars[mi * 16];

    // ---- load W slice into smem once (swizzled 128B rows; row = gate*32 + nloc) ----
    {
#pragma unroll 1
        for (int i = tid; i < 12288; i += 256) {
            int rr = i >> 7, cg = i & 127;
            int s = cg >> 3, c = cg & 7;
            int grow = (rr >> 5) * H_ + n0 + (rr & 31);
            uint32_t dst = sb + (uint32_t)(s * WCH + rr * 128 + ((c ^ (rr & 7)) << 4));
            cpa16(dst, g_w3 + (size_t)grow * H_ + s * 64 + c * 8);
        }
        cpcommit(); cpwait0();
        __syncthreads();
    }

    // ldmatrix lane constants
    const int arow0 = wm + (lane & 15);
    const int acsel = (lane >> 4);
    const int browA = ((lane < 16) ? 0 : 32) + wn8 + (lane & 7);   // LDSM4: gate0 rows / gate1 rows
    const int browC = 64 + wn8 + (lane & 7);                       // LDSM2: gate2 rows
    const int bcsel = (lane >> 3) & 1;

    // epilogue constants: this thread owns rows {wm+mt*16+g4+8*rh} x cols {col2, col2+1}
    const int col2 = n0 + wn8 + 2 * tig;
    float2 bhr = *(const float2*)(bhh + col2);
    float2 bhz = *(const float2*)(bhh + H_ + col2);
    float2 bhn = *(const float2*)(bhh + 2 * H_ + col2);

#pragma unroll 1
    for (int t = 0; t < T_; t++) {
        // gi prefetch (precomputed; independent of barrier)
        float2 gir[4], giz[4], gin[4];
        {
            const float* __restrict__ gi_t = g_gi + (size_t)t * B_ * G_;
#pragma unroll
            for (int q = 0; q < 4; q++) {
                int row = m0 + wm + (q >> 1) * 16 + g4 + 8 * (q & 1);
                const float* p = gi_t + (size_t)row * G_ + col2;
                gir[q] = *(const float2*)(p);
                giz[q] = *(const float2*)(p + H_);
                gin[q] = *(const float2*)(p + 2 * H_);
            }
        }

        // ---- group barrier (32 CTAs sharing this m-slice) ----
        __syncthreads();
        if (tid == 0) {
            __threadfence();
            asm volatile("red.release.gpu.global.add.u32 [%0], 1;" :: "l"(barp) : "memory");
            unsigned v; const unsigned tgt = 32u * (unsigned)(t + 1);
            do { asm volatile("ld.acquire.gpu.global.u32 %0, [%1];" : "=r"(v) : "l"(barp)); } while (v < tgt);
        }
        __syncthreads();

        const __half* __restrict__ Ah = g_hh[t & 1] + (size_t)m0 * H_;

        float acc[2][3][4];
#pragma unroll
        for (int i = 0; i < 2; i++)
#pragma unroll
            for (int j = 0; j < 3; j++)
#pragma unroll
                for (int e = 0; e < 4; e++) acc[i][j][e] = 0.f;

        auto issueA = [&](int s) {
            int buf = s & 3;
            uint32_t ab = ast + (uint32_t)(buf * AST);
            int kc = s * 64;
#pragma unroll
            for (int i = 0; i < 2; i++) {
                int f = tid + 256 * i, r = f >> 3, c = f & 7;
                cpa16(ab + (uint32_t)(r * 128 + ((c ^ (r & 7)) << 4)),
                      Ah + (size_t)r * H_ + kc + c * 8);
            }
            cpcommit();
        };
        issueA(0); issueA(1); issueA(2);
#pragma unroll 1
        for (int s = 0; s < 16; s++) {
            cpwait2();
            __syncthreads();
            uint32_t ab = ast + (uint32_t)((s & 3) * AST);
            uint32_t wb = sb + (uint32_t)(s * WCH);
#pragma unroll
            for (int g = 0; g < 4; g++) {
                uint32_t A0[4], A1[4], B4[4], B2[2];
                {
                    int c = 2 * g + acsel;
                    int r0 = arow0, r1 = arow0 + 16;
                    LDSM4(A0[0], A0[1], A0[2], A0[3], ab + (uint32_t)(r0 * 128 + ((c ^ (r0 & 7)) << 4)));
                    LDSM4(A1[0], A1[1], A1[2], A1[3], ab + (uint32_t)(r1 * 128 + ((c ^ (r1 & 7)) << 4)));
                }
                {
                    int c = 2 * g + bcsel;
                    LDSM4(B4[0], B4[1], B4[2], B4[3], wb + (uint32_t)(browA * 128 + ((c ^ (browA & 7)) << 4)));
                    LDSM2(B2[0], B2[1], wb + (uint32_t)(browC * 128 + ((c ^ (browC & 7)) << 4)));
                }
                mma_f16(acc[0][0], A0[0], A0[1], A0[2], A0[3], B4[0], B4[1]);
                mma_f16(acc[1][0], A1[0], A1[1], A1[2], A1[3], B4[0], B4[1]);
                mma_f16(acc[0][1], A0[0], A0[1], A0[2], A0[3], B4[2], B4[3]);
                mma_f16(acc[1][1], A1[0], A1[1], A1[2], A1[3], B4[2], B4[3]);
                mma_f16(acc[0][2], A0[0], A0[1], A0[2], A0[3], B2[0], B2[1]);
                mma_f16(acc[1][2], A1[0], A1[1], A1[2], A1[3], B2[0], B2[1]);
            }
            if (s + 3 < 16) issueA(s + 3); else cpcommit();
        }
        cpwait0();

        // ---- register-resident gate epilogue ----
        {
            float* __restrict__ hoB = g_hf[(t + 1) & 1];
            __half* __restrict__ hxB = g_hh[(t + 1) & 1];
            const float* __restrict__ hpB = g_hf[t & 1];
#pragma unroll
            for (int q = 0; q < 4; q++) {
                int mt = q >> 1, rh = q & 1;
                int row = m0 + wm + mt * 16 + g4 + 8 * rh;
                float2 hv = *(const float2*)(hpB + (size_t)row * H_ + col2);
                float o0, o1;
                {
                    float rr = sigmoidf_(gir[q].x + acc[mt][0][2 * rh] + bhr.x);
                    float zz = sigmoidf_(giz[q].x + acc[mt][1][2 * rh] + bhz.x);
                    float nn = tanhf(gin[q].x + rr * (acc[mt][2][2 * rh] + bhn.x));
                    o0 = (1.0f - zz) * nn + zz * hv.x;
                }
                {
                    float rr = sigmoidf_(gir[q].y + acc[mt][0][2 * rh + 1] + bhr.y);
                    float zz = sigmoidf_(giz[q].y + acc[mt][1][2 * rh + 1] + bhz.y);
                    float nn = tanhf(gin[q].y + rr * (acc[mt][2][2 * rh + 1] + bhn.y));
                    o1 = (1.0f - zz) * nn + zz * hv.y;
                }
                float2 ov = { o0, o1 };
                *(float2*)(hoB + (size_t)row * H_ + col2) = ov;
                *(__half2*)(hxB + (size_t)row * H_ + col2) = __floats2half2_rn(o0, o1);
            }
        }
        // next iteration's issueA must not overwrite staging before all reads done:
        __syncthreads();
    }
}

// ---------------- output head ----------------
__global__ void out_gemm(const float* __restrict__ Wout, const float* __restrict__ bout, float* __restrict__ out) {
    const int b = blockIdx.x;
    const int wid = threadIdx.x >> 5, lane = threadIdx.x & 31;
    const int o0 = blockIdx.y * 32 + wid * 4;
    const float* __restrict__ h = g_hf[0] + (size_t)b * H_;
    float acc[4] = {0.f, 0.f, 0.f, 0.f};
#pragma unroll
    for (int kk = 0; kk < 8; kk++) {
        int k = kk * 128 + lane * 4;
        float4 hv = *(const float4*)(h + k);
#pragma unroll
        for (int j = 0; j < 4; j++) {
            float4 w = *(const float4*)(Wout + (size_t)(o0 + j) * H_ + k);
            acc[j] += hv.x * w.x + hv.y * w.y + hv.z * w.z + hv.w * w.w;
        }
    }
#pragma unroll
    for (int j = 0; j < 4; j++) {
        float v = acc[j];
#pragma unroll
        for (int s = 16; s > 0; s >>= 1) v += __shfl_xor_sync(0xffffffffu, v, s);
        if (lane == 0) out[(size_t)b * O_ + o0 + j] = v + bout[o0 + j];
    }
}

// ---------------- launch ----------------
extern "C" void kernel_launch(void* const* d_in, const int* in_sizes, int n_in,
                              void* d_out, int out_size) {
    const float* x     = (const float*)d_in[0];
    const float* mask  = (const float*)d_in[1];
    const float* ti    = (const float*)d_in[2];
    const float* W_ih  = (const float*)d_in[3];
    const float* W_hh  = (const float*)d_in[4];
    const float* b_ih  = (const float*)d_in[5];
    const float* b_hh  = (const float*)d_in[6];
    const float* W_out = (const float*)d_in[7];
    const float* b_out = (const float*)d_in[8];
    float* out = (float*)d_out;

    static int smem_set = 0;
    if (!smem_set) {
        cudaFuncSetAttribute(gi_gemm3, cudaFuncAttributeMaxDynamicSharedMemorySize, GI_SMEM);
        cudaFuncSetAttribute(gru_persist, cudaFuncAttributeMaxDynamicSharedMemorySize, P_SMEM);
        smem_set = 1;
    }

    // launch order keeps gru_persist at index 3 (ncu's profile target)
    pack_fused<<<NBX + NBW3 + NBW + NBZ, 256>>>(x, mask, ti, W_ih, W_hh);   // 0
    gi_gemm3<<<dim3((T_ * B_) / 64, G_ / 96), 256, GI_SMEM>>>(b_ih);        // 1
    bar_zero<<<1, 64>>>();                                                  // 2
    gru_persist<<<128, 256, P_SMEM>>>(b_hh);                                // 3 (profiled)
    out_gemm<<<dim3(B_, O_ / 32), 256>>>(W_out, b_out, out);                // 4
}